// round 5
// baseline (speedup 1.0000x reference)
#include <cuda_runtime.h>
#include <cuda_bf16.h>

// Problem constants
#define L 3
#define B 2
#define C 2048
#define HW 3600          // 60*60
#define CH 256
#define KD (L*C)         // 6144, fused K dimension
#define TEMP 20.0f
#define ATT_WT 0.3f

// ---------------- scratch (static __device__ — no allocations) ----------------
__device__ float g_Aq[(size_t)B * KD * HW];   // [b][k][q]  w_l * normalized fq (fp32)
__device__ float g_As[(size_t)B * KD * HW];   // [b][k][s]  normalized fs (fp32)
__device__ float g_red[(size_t)B * HW * HW];  // [b][q][s]  logits -> attn
__device__ float g_invq[L * B * HW];
__device__ float g_invs[L * B * HW];

// ---------------- 1) inverse norms over C (coalesced over spatial) ------------
__global__ void norm_kernel(const float* __restrict__ x, int which) {
    float* inv = which ? g_invs : g_invq;
    int p = blockIdx.x * blockDim.x + threadIdx.x;
    int lb = blockIdx.y;                    // l*B + b
    if (p >= HW) return;
    const float* base = x + (size_t)lb * C * HW + p;
    float s = 0.f;
    #pragma unroll 8
    for (int c = 0; c < C; c++) {
        float v = base[(size_t)c * HW];
        s += v * v;
    }
    float n = sqrtf(s);
    inv[lb * HW + p] = 1.0f / fmaxf(n, 1e-12f);
}

// ---------------- 2) scale + pack (fp32) in [b][k][p] layout ------------------
__global__ void pack_kernel(const float* __restrict__ x, const float* __restrict__ wts,
                            int which) {
    const float* inv = which ? g_invs : g_invq;
    float* out = which ? g_As : g_Aq;
    size_t idx = (size_t)blockIdx.x * blockDim.x + threadIdx.x;
    const size_t total = (size_t)L * B * C * HW;
    if (idx >= total) return;
    int l = (int)(idx / ((size_t)B * C * HW));
    size_t r = idx % ((size_t)B * C * HW);
    int b = (int)(r / ((size_t)C * HW));
    size_t r2 = r % ((size_t)C * HW);
    int c = (int)(r2 / HW);
    int p = (int)(r2 % HW);
    float w = which ? 1.0f : wts[l];
    float v = x[idx] * inv[(l * B + b) * HW + p] * w;
    out[((size_t)b * KD + (size_t)(l * C + c)) * HW + p] = v;
}

// ---------------- 3) big GEMM: red[b][q][s] = sum_k Aq[b][k][q]*As[b][k][s] ---
#define BM 128
#define BN 128
#define BK 16

__global__ __launch_bounds__(256) void gemm1_kernel() {
    int b = blockIdx.z;
    const float* A  = g_Aq + (size_t)b * KD * HW;
    const float* Bm = g_As + (size_t)b * KD * HW;
    float* Cc = g_red + (size_t)b * HW * HW;

    __shared__ float As[BK][BM];
    __shared__ float Bs[BK][BN];

    int m0 = blockIdx.x * BM;
    int n0 = blockIdx.y * BN;
    int tid = threadIdx.x;
    int tx = tid & 15;      // n direction
    int ty = tid >> 4;      // m direction

    float acc[8][8];
    #pragma unroll
    for (int i = 0; i < 8; i++)
        #pragma unroll
        for (int j = 0; j < 8; j++) acc[i][j] = 0.f;

    for (int k0 = 0; k0 < KD; k0 += BK) {
        #pragma unroll
        for (int jj = 0; jj < 8; jj++) {
            int i = tid + jj * 256;
            int kk = i >> 7;
            int mm = i & 127;
            int m = m0 + mm;
            int n = n0 + mm;
            As[kk][mm] = (m < HW) ? A[(size_t)(k0 + kk) * HW + m] : 0.f;
            Bs[kk][mm] = (n < HW) ? Bm[(size_t)(k0 + kk) * HW + n] : 0.f;
        }
        __syncthreads();
        #pragma unroll
        for (int kk = 0; kk < BK; kk++) {
            float a[8], bb[8];
            #pragma unroll
            for (int i = 0; i < 8; i++) a[i] = As[kk][ty * 8 + i];
            #pragma unroll
            for (int j = 0; j < 8; j++) bb[j] = Bs[kk][tx * 8 + j];
            #pragma unroll
            for (int i = 0; i < 8; i++)
                #pragma unroll
                for (int j = 0; j < 8; j++)
                    acc[i][j] += a[i] * bb[j];
        }
        __syncthreads();
    }

    #pragma unroll
    for (int i = 0; i < 8; i++) {
        int m = m0 + ty * 8 + i;
        if (m >= HW) continue;
        #pragma unroll
        for (int j = 0; j < 8; j++) {
            int n = n0 + tx * 8 + j;
            if (n < HW) Cc[(size_t)m * HW + n] = acc[i][j];
        }
    }
}

// ---------------- 4) row softmax over s (in-place, temp applied) --------------
__global__ __launch_bounds__(256) void softmax_kernel() {
    __shared__ float row[HW];
    __shared__ float sred[256];
    size_t base = (size_t)blockIdx.x * HW;   // blockIdx.x = b*HW + q
    int tid = threadIdx.x;

    float mx = -1e30f;
    for (int s = tid; s < HW; s += 256) {
        float v = g_red[base + s] * TEMP;
        row[s] = v;
        mx = fmaxf(mx, v);
    }
    sred[tid] = mx;
    __syncthreads();
    for (int st = 128; st > 0; st >>= 1) {
        if (tid < st) sred[tid] = fmaxf(sred[tid], sred[tid + st]);
        __syncthreads();
    }
    mx = sred[0];
    __syncthreads();

    float sm = 0.f;
    for (int s = tid; s < HW; s += 256) {
        float e = __expf(row[s] - mx);
        row[s] = e;
        sm += e;
    }
    sred[tid] = sm;
    __syncthreads();
    for (int st = 128; st > 0; st >>= 1) {
        if (tid < st) sred[tid] += sred[tid + st];
        __syncthreads();
    }
    float invs = 1.0f / sred[0];
    for (int s = tid; s < HW; s += 256)
        g_red[base + s] = row[s] * invs;
}

// ---------------- 5) attn GEMM + fused epilogue -------------------------------
// att_fq[b][c][q] = sum_s attn[b][q][s] * f_s[b][c][s]
#define BM2 64
#define BN2 64
#define BK2 32

__global__ __launch_bounds__(256) void gemm2_kernel(const float* __restrict__ v,
                                                    const float* __restrict__ fqin,
                                                    float* __restrict__ outfq,
                                                    float* __restrict__ outatt) {
    int b = blockIdx.z;
    const float* A  = g_red + (size_t)b * HW * HW;   // [q][s]
    const float* Bv = v + (size_t)b * CH * HW;       // [c][s]

    int m0 = blockIdx.x * BM2;   // q
    int n0 = blockIdx.y * BN2;   // c

    __shared__ float As[BM2][BK2 + 1];
    __shared__ float Bs[BN2][BK2 + 1];

    int tid = threadIdx.x;
    int tx = tid & 15;      // m (q) direction -> coalesced output
    int ty = tid >> 4;      // n (c) direction

    float acc[4][4];   // acc[j (n)][i (m)]
    #pragma unroll
    for (int j = 0; j < 4; j++)
        #pragma unroll
        for (int i = 0; i < 4; i++) acc[j][i] = 0.f;

    for (int k0 = 0; k0 < HW; k0 += BK2) {
        #pragma unroll
        for (int jj = 0; jj < 8; jj++) {
            int i = tid + jj * 256;
            int mm = i >> 5;
            int kk = i & 31;
            int m = m0 + mm;
            int k = k0 + kk;
            As[mm][kk] = (m < HW && k < HW) ? A[(size_t)m * HW + k] : 0.f;
            int n = n0 + mm;
            Bs[mm][kk] = (k < HW) ? Bv[(size_t)n * HW + k] : 0.f;
        }
        __syncthreads();
        #pragma unroll
        for (int kk = 0; kk < BK2; kk++) {
            float a[4], bb[4];
            #pragma unroll
            for (int i = 0; i < 4; i++) a[i] = As[tx * 4 + i][kk];
            #pragma unroll
            for (int j = 0; j < 4; j++) bb[j] = Bs[ty * 4 + j][kk];
            #pragma unroll
            for (int j = 0; j < 4; j++)
                #pragma unroll
                for (int i = 0; i < 4; i++)
                    acc[j][i] += a[i] * bb[j];
        }
        __syncthreads();
    }

    const float inv13 = 1.0f / (1.0f + ATT_WT);
    #pragma unroll
    for (int j = 0; j < 4; j++) {
        int n = n0 + ty * 4 + j;     // c (always < CH)
        #pragma unroll
        for (int i = 0; i < 4; i++) {
            int m = m0 + tx * 4 + i; // q
            if (m < HW) {
                size_t o = ((size_t)b * CH + n) * HW + m;
                float av = acc[j][i];
                outatt[o] = av;
                outfq[o] = (fqin[o] + av * ATT_WT) * inv13;
            }
        }
    }
}

// ---------------- launch ------------------------------------------------------
extern "C" void kernel_launch(void* const* d_in, const int* in_sizes, int n_in,
                              void* d_out, int out_size) {
    const float* fq_feats = (const float*)d_in[0];
    const float* fs_feats = (const float*)d_in[1];
    const float* f_q      = (const float*)d_in[2];
    const float* f_s      = (const float*)d_in[3];
    const float* w        = (const float*)d_in[4];

    float* outfq  = (float*)d_out;
    float* outatt = outfq + (size_t)B * CH * HW;

    // 1) inverse norms
    dim3 gN((HW + 255) / 256, L * B);
    norm_kernel<<<gN, 256>>>(fq_feats, 0);
    norm_kernel<<<gN, 256>>>(fs_feats, 1);

    // 2) pack (fp32) to [b][k][p]
    size_t total = (size_t)L * B * C * HW;
    int pb = (int)((total + 255) / 256);
    pack_kernel<<<pb, 256>>>(fq_feats, w, 0);
    pack_kernel<<<pb, 256>>>(fs_feats, w, 1);

    // 3) red = (w-scaled fq_n)^T @ fs_n   (M=N=3600, K=6144, per batch)
    dim3 g1((HW + BM - 1) / BM, (HW + BN - 1) / BN, B);
    gemm1_kernel<<<g1, 256>>>();

    // 4) softmax over support positions
    softmax_kernel<<<B * HW, 256>>>();

    // 5) attn @ v + epilogue
    dim3 g2((HW + BM2 - 1) / BM2, CH / BN2, B);
    gemm2_kernel<<<g2, 256>>>(f_s, f_q, outfq, outatt);
}

// round 6
// speedup vs baseline: 1.0003x; 1.0003x over previous
#include <cuda_runtime.h>
#include <cuda_bf16.h>

// Problem constants
#define L 3
#define B 2
#define C 2048
#define HW 3600          // 60*60
#define CH 256
#define KD (L*C)         // 6144, fused K dimension
#define TEMP 20.0f
#define ATT_WT 0.3f

// ---------------- scratch (static __device__ — no allocations) ----------------
__device__ float g_Aq[(size_t)B * KD * HW];   // [b][k][q]  w_l * normalized fq (fp32)
__device__ float g_As[(size_t)B * KD * HW];   // [b][k][s]  normalized fs (fp32)
__device__ float g_red[(size_t)B * HW * HW];  // [b][q][s]  logits -> attn
__device__ float g_invq[L * B * HW];
__device__ float g_invs[L * B * HW];

// ---------------- 1) inverse norms over C (coalesced over spatial) ------------
__global__ void norm_kernel(const float* __restrict__ x, int which) {
    float* inv = which ? g_invs : g_invq;
    int p = blockIdx.x * blockDim.x + threadIdx.x;
    int lb = blockIdx.y;                    // l*B + b
    if (p >= HW) return;
    const float* base = x + (size_t)lb * C * HW + p;
    float s = 0.f;
    #pragma unroll 8
    for (int c = 0; c < C; c++) {
        float v = base[(size_t)c * HW];
        s += v * v;
    }
    float n = sqrtf(s);
    inv[lb * HW + p] = 1.0f / fmaxf(n, 1e-12f);
}

// ---------------- 2) scale + pack (fp32) in [b][k][p] layout ------------------
__global__ void pack_kernel(const float* __restrict__ x, const float* __restrict__ wts,
                            int which) {
    const float* inv = which ? g_invs : g_invq;
    float* out = which ? g_As : g_Aq;
    size_t idx = (size_t)blockIdx.x * blockDim.x + threadIdx.x;
    const size_t total = (size_t)L * B * C * HW;
    if (idx >= total) return;
    int l = (int)(idx / ((size_t)B * C * HW));
    size_t r = idx % ((size_t)B * C * HW);
    int b = (int)(r / ((size_t)C * HW));
    size_t r2 = r % ((size_t)C * HW);
    int c = (int)(r2 / HW);
    int p = (int)(r2 % HW);
    float w = which ? 1.0f : wts[l];
    float v = x[idx] * inv[(l * B + b) * HW + p] * w;
    out[((size_t)b * KD + (size_t)(l * C + c)) * HW + p] = v;
}

// ---------------- 3) big GEMM: red[b][q][s] = sum_k Aq[b][k][q]*As[b][k][s] ---
#define BM 128
#define BN 128
#define BK 16

__global__ __launch_bounds__(256) void gemm1_kernel() {
    int b = blockIdx.z;
    const float* A  = g_Aq + (size_t)b * KD * HW;
    const float* Bm = g_As + (size_t)b * KD * HW;
    float* Cc = g_red + (size_t)b * HW * HW;

    __shared__ float As[BK][BM];
    __shared__ float Bs[BK][BN];

    int m0 = blockIdx.x * BM;
    int n0 = blockIdx.y * BN;
    int tid = threadIdx.x;
    int tx = tid & 15;      // n direction
    int ty = tid >> 4;      // m direction

    float acc[8][8];
    #pragma unroll
    for (int i = 0; i < 8; i++)
        #pragma unroll
        for (int j = 0; j < 8; j++) acc[i][j] = 0.f;

    for (int k0 = 0; k0 < KD; k0 += BK) {
        #pragma unroll
        for (int jj = 0; jj < 8; jj++) {
            int i = tid + jj * 256;
            int kk = i >> 7;
            int mm = i & 127;
            int m = m0 + mm;
            int n = n0 + mm;
            As[kk][mm] = (m < HW) ? A[(size_t)(k0 + kk) * HW + m] : 0.f;
            Bs[kk][mm] = (n < HW) ? Bm[(size_t)(k0 + kk) * HW + n] : 0.f;
        }
        __syncthreads();
        #pragma unroll
        for (int kk = 0; kk < BK; kk++) {
            float a[8], bb[8];
            #pragma unroll
            for (int i = 0; i < 8; i++) a[i] = As[kk][ty * 8 + i];
            #pragma unroll
            for (int j = 0; j < 8; j++) bb[j] = Bs[kk][tx * 8 + j];
            #pragma unroll
            for (int i = 0; i < 8; i++)
                #pragma unroll
                for (int j = 0; j < 8; j++)
                    acc[i][j] += a[i] * bb[j];
        }
        __syncthreads();
    }

    #pragma unroll
    for (int i = 0; i < 8; i++) {
        int m = m0 + ty * 8 + i;
        if (m >= HW) continue;
        #pragma unroll
        for (int j = 0; j < 8; j++) {
            int n = n0 + tx * 8 + j;
            if (n < HW) Cc[(size_t)m * HW + n] = acc[i][j];
        }
    }
}

// ---------------- 4) row softmax over s (in-place, temp applied) --------------
__global__ __launch_bounds__(256) void softmax_kernel() {
    __shared__ float row[HW];
    __shared__ float sred[256];
    size_t base = (size_t)blockIdx.x * HW;   // blockIdx.x = b*HW + q
    int tid = threadIdx.x;

    float mx = -1e30f;
    for (int s = tid; s < HW; s += 256) {
        float v = g_red[base + s] * TEMP;
        row[s] = v;
        mx = fmaxf(mx, v);
    }
    sred[tid] = mx;
    __syncthreads();
    for (int st = 128; st > 0; st >>= 1) {
        if (tid < st) sred[tid] = fmaxf(sred[tid], sred[tid + st]);
        __syncthreads();
    }
    mx = sred[0];
    __syncthreads();

    float sm = 0.f;
    for (int s = tid; s < HW; s += 256) {
        float e = __expf(row[s] - mx);
        row[s] = e;
        sm += e;
    }
    sred[tid] = sm;
    __syncthreads();
    for (int st = 128; st > 0; st >>= 1) {
        if (tid < st) sred[tid] += sred[tid + st];
        __syncthreads();
    }
    float invs = 1.0f / sred[0];
    for (int s = tid; s < HW; s += 256)
        g_red[base + s] = row[s] * invs;
}

// ---------------- 5) attn GEMM + fused epilogue -------------------------------
// att_fq[b][c][q] = sum_s attn[b][q][s] * f_s[b][c][s]
#define BM2 64
#define BN2 64
#define BK2 32

__global__ __launch_bounds__(256) void gemm2_kernel(const float* __restrict__ v,
                                                    const float* __restrict__ fqin,
                                                    float* __restrict__ outfq,
                                                    float* __restrict__ outatt) {
    int b = blockIdx.z;
    const float* A  = g_red + (size_t)b * HW * HW;   // [q][s]
    const float* Bv = v + (size_t)b * CH * HW;       // [c][s]

    int m0 = blockIdx.x * BM2;   // q
    int n0 = blockIdx.y * BN2;   // c

    __shared__ float As[BM2][BK2 + 1];
    __shared__ float Bs[BN2][BK2 + 1];

    int tid = threadIdx.x;
    int tx = tid & 15;      // m (q) direction -> coalesced output
    int ty = tid >> 4;      // n (c) direction

    float acc[4][4];   // acc[j (n)][i (m)]
    #pragma unroll
    for (int j = 0; j < 4; j++)
        #pragma unroll
        for (int i = 0; i < 4; i++) acc[j][i] = 0.f;

    for (int k0 = 0; k0 < HW; k0 += BK2) {
        #pragma unroll
        for (int jj = 0; jj < 8; jj++) {
            int i = tid + jj * 256;
            int mm = i >> 5;
            int kk = i & 31;
            int m = m0 + mm;
            int k = k0 + kk;
            As[mm][kk] = (m < HW && k < HW) ? A[(size_t)m * HW + k] : 0.f;
            int n = n0 + mm;
            Bs[mm][kk] = (k < HW) ? Bv[(size_t)n * HW + k] : 0.f;
        }
        __syncthreads();
        #pragma unroll
        for (int kk = 0; kk < BK2; kk++) {
            float a[4], bb[4];
            #pragma unroll
            for (int i = 0; i < 4; i++) a[i] = As[tx * 4 + i][kk];
            #pragma unroll
            for (int j = 0; j < 4; j++) bb[j] = Bs[ty * 4 + j][kk];
            #pragma unroll
            for (int j = 0; j < 4; j++)
                #pragma unroll
                for (int i = 0; i < 4; i++)
                    acc[j][i] += a[i] * bb[j];
        }
        __syncthreads();
    }

    const float inv13 = 1.0f / (1.0f + ATT_WT);
    #pragma unroll
    for (int j = 0; j < 4; j++) {
        int n = n0 + ty * 4 + j;     // c (always < CH)
        #pragma unroll
        for (int i = 0; i < 4; i++) {
            int m = m0 + tx * 4 + i; // q
            if (m < HW) {
                size_t o = ((size_t)b * CH + n) * HW + m;
                float av = acc[j][i];
                outatt[o] = av;
                outfq[o] = (fqin[o] + av * ATT_WT) * inv13;
            }
        }
    }
}

// ---------------- launch ------------------------------------------------------
extern "C" void kernel_launch(void* const* d_in, const int* in_sizes, int n_in,
                              void* d_out, int out_size) {
    const float* fq_feats = (const float*)d_in[0];
    const float* fs_feats = (const float*)d_in[1];
    const float* f_q      = (const float*)d_in[2];
    const float* f_s      = (const float*)d_in[3];
    const float* w        = (const float*)d_in[4];

    float* outfq  = (float*)d_out;
    float* outatt = outfq + (size_t)B * CH * HW;

    // 1) inverse norms
    dim3 gN((HW + 255) / 256, L * B);
    norm_kernel<<<gN, 256>>>(fq_feats, 0);
    norm_kernel<<<gN, 256>>>(fs_feats, 1);

    // 2) pack (fp32) to [b][k][p]
    size_t total = (size_t)L * B * C * HW;
    int pb = (int)((total + 255) / 256);
    pack_kernel<<<pb, 256>>>(fq_feats, w, 0);
    pack_kernel<<<pb, 256>>>(fs_feats, w, 1);

    // 3) red = (w-scaled fq_n)^T @ fs_n   (M=N=3600, K=6144, per batch)
    dim3 g1((HW + BM - 1) / BM, (HW + BN - 1) / BN, B);
    gemm1_kernel<<<g1, 256>>>();

    // 4) softmax over support positions
    softmax_kernel<<<B * HW, 256>>>();

    // 5) attn @ v + epilogue
    dim3 g2((HW + BM2 - 1) / BM2, CH / BN2, B);
    gemm2_kernel<<<g2, 256>>>(f_s, f_q, outfq, outatt);
}

// round 7
// speedup vs baseline: 1.0035x; 1.0032x over previous
#include <cuda_runtime.h>
#include <cuda_bf16.h>

// Problem constants
#define L 3
#define B 2
#define C 2048
#define HW 3600          // 60*60
#define CH 256
#define KD (L*C)         // 6144, fused K dimension
#define TEMP 20.0f
#define ATT_WT 0.3f

// ---------------- scratch (static __device__ — no allocations) ----------------
__device__ float g_Aq[(size_t)B * KD * HW];   // [b][k][q]  w_l * normalized fq (fp32)
__device__ float g_As[(size_t)B * KD * HW];   // [b][k][s]  normalized fs (fp32)
__device__ float g_red[(size_t)B * HW * HW];  // [b][q][s]  logits -> attn
__device__ float g_invq[L * B * HW];
__device__ float g_invs[L * B * HW];

// ---------------- 1) inverse norms over C (coalesced over spatial) ------------
__global__ void norm_kernel(const float* __restrict__ x, int which) {
    float* inv = which ? g_invs : g_invq;
    int p = blockIdx.x * blockDim.x + threadIdx.x;
    int lb = blockIdx.y;                    // l*B + b
    if (p >= HW) return;
    const float* base = x + (size_t)lb * C * HW + p;
    float s = 0.f;
    #pragma unroll 8
    for (int c = 0; c < C; c++) {
        float v = base[(size_t)c * HW];
        s += v * v;
    }
    float n = sqrtf(s);
    inv[lb * HW + p] = 1.0f / fmaxf(n, 1e-12f);
}

// ---------------- 2) scale + pack (fp32) in [b][k][p] layout ------------------
__global__ void pack_kernel(const float* __restrict__ x, const float* __restrict__ wts,
                            int which) {
    const float* inv = which ? g_invs : g_invq;
    float* out = which ? g_As : g_Aq;
    size_t idx = (size_t)blockIdx.x * blockDim.x + threadIdx.x;
    const size_t total = (size_t)L * B * C * HW;
    if (idx >= total) return;
    int l = (int)(idx / ((size_t)B * C * HW));
    size_t r = idx % ((size_t)B * C * HW);
    int b = (int)(r / ((size_t)C * HW));
    size_t r2 = r % ((size_t)C * HW);
    int c = (int)(r2 / HW);
    int p = (int)(r2 % HW);
    float w = which ? 1.0f : wts[l];
    float v = x[idx] * inv[(l * B + b) * HW + p] * w;
    out[((size_t)b * KD + (size_t)(l * C + c)) * HW + p] = v;
}

// ---------------- 3) big GEMM: red[b][q][s] = sum_k Aq[b][k][q]*As[b][k][s] ---
#define BM 128
#define BN 128
#define BK 16

__global__ __launch_bounds__(256) void gemm1_kernel() {
    int b = blockIdx.z;
    const float* A  = g_Aq + (size_t)b * KD * HW;
    const float* Bm = g_As + (size_t)b * KD * HW;
    float* Cc = g_red + (size_t)b * HW * HW;

    __shared__ float As[BK][BM];
    __shared__ float Bs[BK][BN];

    int m0 = blockIdx.x * BM;
    int n0 = blockIdx.y * BN;
    int tid = threadIdx.x;
    int tx = tid & 15;      // n direction
    int ty = tid >> 4;      // m direction

    float acc[8][8];
    #pragma unroll
    for (int i = 0; i < 8; i++)
        #pragma unroll
        for (int j = 0; j < 8; j++) acc[i][j] = 0.f;

    for (int k0 = 0; k0 < KD; k0 += BK) {
        #pragma unroll
        for (int jj = 0; jj < 8; jj++) {
            int i = tid + jj * 256;
            int kk = i >> 7;
            int mm = i & 127;
            int m = m0 + mm;
            int n = n0 + mm;
            As[kk][mm] = (m < HW) ? A[(size_t)(k0 + kk) * HW + m] : 0.f;
            Bs[kk][mm] = (n < HW) ? Bm[(size_t)(k0 + kk) * HW + n] : 0.f;
        }
        __syncthreads();
        #pragma unroll
        for (int kk = 0; kk < BK; kk++) {
            float a[8], bb[8];
            #pragma unroll
            for (int i = 0; i < 8; i++) a[i] = As[kk][ty * 8 + i];
            #pragma unroll
            for (int j = 0; j < 8; j++) bb[j] = Bs[kk][tx * 8 + j];
            #pragma unroll
            for (int i = 0; i < 8; i++)
                #pragma unroll
                for (int j = 0; j < 8; j++)
                    acc[i][j] += a[i] * bb[j];
        }
        __syncthreads();
    }

    #pragma unroll
    for (int i = 0; i < 8; i++) {
        int m = m0 + ty * 8 + i;
        if (m >= HW) continue;
        #pragma unroll
        for (int j = 0; j < 8; j++) {
            int n = n0 + tx * 8 + j;
            if (n < HW) Cc[(size_t)m * HW + n] = acc[i][j];
        }
    }
}

// ---------------- 4) row softmax over s (in-place, temp applied) --------------
__global__ __launch_bounds__(256) void softmax_kernel() {
    __shared__ float row[HW];
    __shared__ float sred[256];
    size_t base = (size_t)blockIdx.x * HW;   // blockIdx.x = b*HW + q
    int tid = threadIdx.x;

    float mx = -1e30f;
    for (int s = tid; s < HW; s += 256) {
        float v = g_red[base + s] * TEMP;
        row[s] = v;
        mx = fmaxf(mx, v);
    }
    sred[tid] = mx;
    __syncthreads();
    for (int st = 128; st > 0; st >>= 1) {
        if (tid < st) sred[tid] = fmaxf(sred[tid], sred[tid + st]);
        __syncthreads();
    }
    mx = sred[0];
    __syncthreads();

    float sm = 0.f;
    for (int s = tid; s < HW; s += 256) {
        float e = __expf(row[s] - mx);
        row[s] = e;
        sm += e;
    }
    sred[tid] = sm;
    __syncthreads();
    for (int st = 128; st > 0; st >>= 1) {
        if (tid < st) sred[tid] += sred[tid + st];
        __syncthreads();
    }
    float invs = 1.0f / sred[0];
    for (int s = tid; s < HW; s += 256)
        g_red[base + s] = row[s] * invs;
}

// ---------------- 5) attn GEMM + fused epilogue -------------------------------
// att_fq[b][c][q] = sum_s attn[b][q][s] * f_s[b][c][s]
#define BM2 64
#define BN2 64
#define BK2 32

__global__ __launch_bounds__(256) void gemm2_kernel(const float* __restrict__ v,
                                                    const float* __restrict__ fqin,
                                                    float* __restrict__ outfq,
                                                    float* __restrict__ outatt) {
    int b = blockIdx.z;
    const float* A  = g_red + (size_t)b * HW * HW;   // [q][s]
    const float* Bv = v + (size_t)b * CH * HW;       // [c][s]

    int m0 = blockIdx.x * BM2;   // q
    int n0 = blockIdx.y * BN2;   // c

    __shared__ float As[BM2][BK2 + 1];
    __shared__ float Bs[BN2][BK2 + 1];

    int tid = threadIdx.x;
    int tx = tid & 15;      // m (q) direction -> coalesced output
    int ty = tid >> 4;      // n (c) direction

    float acc[4][4];   // acc[j (n)][i (m)]
    #pragma unroll
    for (int j = 0; j < 4; j++)
        #pragma unroll
        for (int i = 0; i < 4; i++) acc[j][i] = 0.f;

    for (int k0 = 0; k0 < HW; k0 += BK2) {
        #pragma unroll
        for (int jj = 0; jj < 8; jj++) {
            int i = tid + jj * 256;
            int mm = i >> 5;
            int kk = i & 31;
            int m = m0 + mm;
            int k = k0 + kk;
            As[mm][kk] = (m < HW && k < HW) ? A[(size_t)m * HW + k] : 0.f;
            int n = n0 + mm;
            Bs[mm][kk] = (k < HW) ? Bv[(size_t)n * HW + k] : 0.f;
        }
        __syncthreads();
        #pragma unroll
        for (int kk = 0; kk < BK2; kk++) {
            float a[4], bb[4];
            #pragma unroll
            for (int i = 0; i < 4; i++) a[i] = As[tx * 4 + i][kk];
            #pragma unroll
            for (int j = 0; j < 4; j++) bb[j] = Bs[ty * 4 + j][kk];
            #pragma unroll
            for (int j = 0; j < 4; j++)
                #pragma unroll
                for (int i = 0; i < 4; i++)
                    acc[j][i] += a[i] * bb[j];
        }
        __syncthreads();
    }

    const float inv13 = 1.0f / (1.0f + ATT_WT);
    #pragma unroll
    for (int j = 0; j < 4; j++) {
        int n = n0 + ty * 4 + j;     // c (always < CH)
        #pragma unroll
        for (int i = 0; i < 4; i++) {
            int m = m0 + tx * 4 + i; // q
            if (m < HW) {
                size_t o = ((size_t)b * CH + n) * HW + m;
                float av = acc[j][i];
                outatt[o] = av;
                outfq[o] = (fqin[o] + av * ATT_WT) * inv13;
            }
        }
    }
}

// ---------------- launch ------------------------------------------------------
extern "C" void kernel_launch(void* const* d_in, const int* in_sizes, int n_in,
                              void* d_out, int out_size) {
    const float* fq_feats = (const float*)d_in[0];
    const float* fs_feats = (const float*)d_in[1];
    const float* f_q      = (const float*)d_in[2];
    const float* f_s      = (const float*)d_in[3];
    const float* w        = (const float*)d_in[4];

    float* outfq  = (float*)d_out;
    float* outatt = outfq + (size_t)B * CH * HW;

    // 1) inverse norms
    dim3 gN((HW + 255) / 256, L * B);
    norm_kernel<<<gN, 256>>>(fq_feats, 0);
    norm_kernel<<<gN, 256>>>(fs_feats, 1);

    // 2) pack (fp32) to [b][k][p]
    size_t total = (size_t)L * B * C * HW;
    int pb = (int)((total + 255) / 256);
    pack_kernel<<<pb, 256>>>(fq_feats, w, 0);
    pack_kernel<<<pb, 256>>>(fs_feats, w, 1);

    // 3) red = (w-scaled fq_n)^T @ fs_n   (M=N=3600, K=6144, per batch)
    dim3 g1((HW + BM - 1) / BM, (HW + BN - 1) / BN, B);
    gemm1_kernel<<<g1, 256>>>();

    // 4) softmax over support positions
    softmax_kernel<<<B * HW, 256>>>();

    // 5) attn @ v + epilogue
    dim3 g2((HW + BM2 - 1) / BM2, CH / BN2, B);
    gemm2_kernel<<<g2, 256>>>(f_s, f_q, outfq, outatt);
}